// round 13
// baseline (speedup 1.0000x reference)
#include <cuda_runtime.h>
#include <cuda_bf16.h>
#include <cstdint>
#include <cstddef>

// Problem dims
#define BB   64
#define TT   2048
#define ID   1024
#define HD   1024
#define OD   512

// ---------------------------------------------------------------------------
// Scratch (__device__ globals)
// ---------------------------------------------------------------------------
__device__ float         g_pre[(size_t)TT * BB * HD];        // [t][b][h]  (512 MB)
__device__ __nv_bfloat16 g_abf[(size_t)BB * TT * 2048];      // split X [hi|lo] (512 MB)
__device__ __nv_bfloat16 g_wbf[(size_t)HD * 2048];           // split W_ih [hi|lo] (4 MB)
__device__ __nv_bfloat16 g_hbf[2][2][BB][HD];                // h double-buf, hi/lo (0.5 MB)
__device__ float         g_h[BB * HD];                       // final hidden state
__device__ __align__(128) unsigned g_cnt4[4][32];            // 4 groups; slots 0,8,16,24 used

// ---------------------------------------------------------------------------
// Generic-PTX helpers (safe for compute_103 target: no tcgen05/TMA)
// ---------------------------------------------------------------------------
__device__ __forceinline__ uint32_t smem_to_u32(const void* p) {
    uint32_t a;
    asm("{ .reg .u64 t; cvta.to.shared.u64 t, %1; cvt.u32.u64 %0, t; }"
        : "=r"(a) : "l"(p));
    return a;
}
__device__ __forceinline__ void cp16(uint32_t saddr, const void* g) {
    asm volatile("cp.async.cg.shared.global [%0], [%1], 16;"
                 :: "r"(saddr), "l"(g) : "memory");
}
#define CP_COMMIT() asm volatile("cp.async.commit_group;" ::: "memory")
#define CP_WAIT1()  asm volatile("cp.async.wait_group 1;" ::: "memory")
#define CP_WAIT0()  asm volatile("cp.async.wait_group 0;" ::: "memory")

__device__ __forceinline__ void ldsm_x4(uint32_t& r0, uint32_t& r1,
                                        uint32_t& r2, uint32_t& r3, uint32_t a) {
    asm volatile("ldmatrix.sync.aligned.m8n8.x4.shared.b16 {%0,%1,%2,%3}, [%4];"
                 : "=r"(r0), "=r"(r1), "=r"(r2), "=r"(r3) : "r"(a));
}
__device__ __forceinline__ void mma16816(float* c, const uint32_t* a,
                                         uint32_t b0, uint32_t b1) {
    asm volatile(
        "mma.sync.aligned.m16n8k16.row.col.f32.bf16.bf16.f32 "
        "{%0,%1,%2,%3}, {%4,%5,%6,%7}, {%8,%9}, {%0,%1,%2,%3};"
        : "+f"(c[0]), "+f"(c[1]), "+f"(c[2]), "+f"(c[3])
        : "r"(a[0]), "r"(a[1]), "r"(a[2]), "r"(a[3]), "r"(b0), "r"(b1));
}

// Accurate tanh built from EX2 (avoids tanh.approx under fast-math)
__device__ __forceinline__ float tanh_acc(float x) {
    float ax = fabsf(x);
    float e  = exp2f(ax * 2.885390081777927f);     // e^{2|x|}
    float r  = 1.0f - 2.0f / (e + 1.0f);
    return (x < 0.0f) ? -r : r;
}

// ---------------------------------------------------------------------------
// init: zero h buffer 0 (hi+lo) and the barrier counters.
// ---------------------------------------------------------------------------
__global__ __launch_bounds__(256) void init_kernel() {
    unsigned i = blockIdx.x * 256u + threadIdx.x;          // 0..65535
    ((uint32_t*)g_hbf)[i] = 0u;                            // g_hbf[0][*][*][*]
    if (i < 128) ((unsigned*)g_cnt4)[i] = 0u;
}

// ---------------------------------------------------------------------------
// bf16 2-term split precompute: rows are [hi(1024) | lo(1024)].
// ---------------------------------------------------------------------------
__device__ __forceinline__ void split4(float4 v, ushort4& h, ushort4& l) {
    __nv_bfloat16 hx = __float2bfloat16(v.x);
    __nv_bfloat16 hy = __float2bfloat16(v.y);
    __nv_bfloat16 hz = __float2bfloat16(v.z);
    __nv_bfloat16 hw = __float2bfloat16(v.w);
    h.x = __bfloat16_as_ushort(hx); h.y = __bfloat16_as_ushort(hy);
    h.z = __bfloat16_as_ushort(hz); h.w = __bfloat16_as_ushort(hw);
    l.x = __bfloat16_as_ushort(__float2bfloat16(v.x - __bfloat162float(hx)));
    l.y = __bfloat16_as_ushort(__float2bfloat16(v.y - __bfloat162float(hy)));
    l.z = __bfloat16_as_ushort(__float2bfloat16(v.z - __bfloat162float(hz)));
    l.w = __bfloat16_as_ushort(__float2bfloat16(v.w - __bfloat162float(hw)));
}

__global__ __launch_bounds__(256) void split_x_kernel(const float* __restrict__ X) {
    const size_t n4 = (size_t)BB * TT * ID / 4;
    size_t stride = (size_t)gridDim.x * blockDim.x;
    for (size_t i = (size_t)blockIdx.x * blockDim.x + threadIdx.x; i < n4; i += stride) {
        size_t m  = i >> 8;
        int    k4 = (int)(i & 255);
        float4 v  = ((const float4*)X)[i];
        ushort4 h, l; split4(v, h, l);
        ushort4* row = (ushort4*)(g_abf + m * 2048);
        row[k4] = h; row[256 + k4] = l;
    }
}

__global__ __launch_bounds__(256) void split_w_kernel(const float* __restrict__ W) {
    const size_t n4 = (size_t)HD * ID / 4;
    size_t stride = (size_t)gridDim.x * blockDim.x;
    for (size_t i = (size_t)blockIdx.x * blockDim.x + threadIdx.x; i < n4; i += stride) {
        size_t m  = i >> 8;
        int    k4 = (int)(i & 255);
        float4 v  = ((const float4*)W)[i];
        ushort4 h, l; split4(v, h, l);
        ushort4* row = (ushort4*)(g_wbf + m * 2048);
        row[k4] = h; row[256 + k4] = l;
    }
}

// ---------------------------------------------------------------------------
// Phase 1 (mma.sync bf16): pre = X @ W_ih^T + b_h.
// 3-stage cp.async pipeline, dynamic smem, one __syncthreads per stage. (R12)
// ---------------------------------------------------------------------------
#define P1_STRIDE 40
#define P1_NSTG   96
#define P1_BUF    (128 * P1_STRIDE)                 // elems per array per stage
#define P1_SMEM_BYTES (3 * 2 * P1_BUF * 2)          // 61440

__global__ __launch_bounds__(256, 2) void phase1_mma_kernel(const float* __restrict__ bh)
{
    extern __shared__ __nv_bfloat16 p1sm[];

    const int tid  = threadIdx.x;
    const int bn   = blockIdx.x;          // 0..7
    const int bm   = blockIdx.y;          // 0..1023
    const int wid  = tid >> 5, lane = tid & 31;
    const int wm   = wid & 1;
    const int wn   = wid >> 1;

    const __nv_bfloat16* Ag = g_abf + (size_t)(bm * 128) * 2048;
    const __nv_bfloat16* Bg = g_wbf + (size_t)(bn * 128) * 2048;

    const uint32_t sA = smem_to_u32(p1sm);
    const uint32_t sB = sA + 3 * P1_BUF * 2;
    const int lr = tid >> 2, lq = tid & 3;

    float acc[4][4][4];
#pragma unroll
    for (int i = 0; i < 4; ++i)
#pragma unroll
        for (int j = 0; j < 4; ++j)
#pragma unroll
            for (int k = 0; k < 4; ++k) acc[i][j][k] = 0.0f;

#define LOAD_STAGE(kt, buf) do {                                                  \
    int aoff = (((kt) < 32) ? (kt) : ((kt) - 32)) * 32;                           \
    int woff = (((kt) < 64) ? (kt) : ((kt) - 64)) * 32;                           \
    const __nv_bfloat16* ag = Ag + (size_t)lr * 2048 + aoff + lq * 8;             \
    const __nv_bfloat16* bg = Bg + (size_t)lr * 2048 + woff + lq * 8;             \
    uint32_t da = sA + (uint32_t)((buf) * P1_BUF + lr * P1_STRIDE + lq * 8) * 2;  \
    uint32_t db = sB + (uint32_t)((buf) * P1_BUF + lr * P1_STRIDE + lq * 8) * 2;  \
    cp16(da, ag); cp16(da + 64 * P1_STRIDE * 2, ag + (size_t)64 * 2048);          \
    cp16(db, bg); cp16(db + 64 * P1_STRIDE * 2, bg + (size_t)64 * 2048);          \
} while (0)

    LOAD_STAGE(0, 0); CP_COMMIT();
    LOAD_STAGE(1, 1); CP_COMMIT();

    const int lrow  = lane & 15;
    const int lhalf = lane >> 4;

    int buf = 0;
    for (int kt = 0; kt < P1_NSTG; ++kt) {
        if (kt < P1_NSTG - 1) { CP_WAIT1(); } else { CP_WAIT0(); }
        __syncthreads();

        if (kt + 2 < P1_NSTG) {
            int bld = buf + 2; if (bld >= 3) bld -= 3;
            LOAD_STAGE(kt + 2, bld); CP_COMMIT();
        }

        const uint32_t abase = sA + (uint32_t)(buf * P1_BUF) * 2;
        const uint32_t bbase = sB + (uint32_t)(buf * P1_BUF) * 2;

#pragma unroll
        for (int ks = 0; ks < 2; ++ks) {
            uint32_t a[4][4];
#pragma unroll
            for (int mt = 0; mt < 4; ++mt) {
                uint32_t ad = abase +
                    (uint32_t)((wm * 64 + mt * 16 + lrow) * P1_STRIDE + ks * 16 + lhalf * 8) * 2;
                ldsm_x4(a[mt][0], a[mt][1], a[mt][2], a[mt][3], ad);
            }
            uint32_t bf[2][4];
#pragma unroll
            for (int bp = 0; bp < 2; ++bp) {
                uint32_t bd = bbase +
                    (uint32_t)((wn * 32 + bp * 16 + lrow) * P1_STRIDE + ks * 16 + lhalf * 8) * 2;
                ldsm_x4(bf[bp][0], bf[bp][1], bf[bp][2], bf[bp][3], bd);
            }
#pragma unroll
            for (int mt = 0; mt < 4; ++mt)
#pragma unroll
                for (int nt = 0; nt < 4; ++nt)
                    mma16816(acc[mt][nt], a[mt],
                             bf[nt >> 1][nt & 1], bf[nt >> 1][(nt & 1) + 2]);
        }

        if (++buf == 3) buf = 0;
    }
#undef LOAD_STAGE

    const int col0 = bn * 128 + wn * 32;
#pragma unroll
    for (int mt = 0; mt < 4; ++mt) {
#pragma unroll
        for (int half = 0; half < 2; ++half) {
            int m  = bm * 128 + wm * 64 + mt * 16 + (lane >> 2) + half * 8;
            int b_ = m >> 11;
            int t_ = m & (TT - 1);
            float* orow = g_pre + ((size_t)t_ * BB + b_) * HD;
#pragma unroll
            for (int nt = 0; nt < 4; ++nt) {
                int c = col0 + nt * 8 + (lane & 3) * 2;
                float2 v;
                v.x = acc[mt][nt][half * 2 + 0] + __ldg(bh + c);
                v.y = acc[mt][nt][half * 2 + 1] + __ldg(bh + c + 1);
                *(float2*)(orow + c) = v;
            }
        }
    }
}

// ---------------------------------------------------------------------------
// Phase 2: persistent recurrence (R12 barrier, NEW hi/lo overlapped h-load).
// 128 CTAs = 4 batch-groups(16 rows) x 32 col-groups(32 cols), 256 threads.
// 8 warps = 2 warpsets: set0 k[0,512), set1 k[512,1024).
// h-load: hi as cp.async group 1, lo as group 2. Pass 1 (A=Wh*hh, B=Wl*hh)
// starts after WAIT1 (hi only); pass 2 (C=Wh*hl) after WAIT0 — lo transfer
// overlaps pass-1 compute.
// Barrier (PROVEN, unchanged): fence + atomicAdd to 4 spread counters +
// volatile 4-load sum poll + trailing fence.
// ---------------------------------------------------------------------------
#define WS        1032                       // bf16 elems per smem row (129*16B)
#define SM_WHI    0
#define SM_WLO    (32 * WS)
#define SM_HHH    (64 * WS)
#define SM_HHL    (80 * WS)
#define SM_STGF   (96 * WS)                  // float staging [2][16][33] after this
#define R4_SMEM   (96 * WS * 2 + 2 * 16 * 33 * 4)   // 202368

__global__ __launch_bounds__(256, 1) void recur4_kernel(const float* __restrict__ Whh)
{
    extern __shared__ __nv_bfloat16 sm[];
    float* stg = (float*)&sm[SM_STGF];       // [2][16][33]
    const int tid  = threadIdx.x;
    const int lane = tid & 31, wid = tid >> 5;
    const int wset = wid >> 2;               // k-half
    const int w4   = wid & 3;
    const int wi   = w4 & 1;                 // col half (16 cols)
    const int wj   = w4 >> 1;                // batch half (8 rows)
    const int bg   = blockIdx.x >> 5;        // 0..3
    const int cg   = blockIdx.x & 31;        // 0..31
    const uint32_t sb = smem_to_u32(sm);

    // ---- persistent W_hh slice [32 cols][1024 k], split hi/lo ----
    for (int e = tid; e < 32 * 1024; e += 256) {
        int n = e >> 10, k = e & 1023;
        float v = Whh[(size_t)(cg * 32 + n) * HD + k];
        __nv_bfloat16 h = __float2bfloat16(v);
        sm[SM_WHI + n * WS + k] = h;
        sm[SM_WLO + n * WS + k] = __float2bfloat16(v - __bfloat162float(h));
    }

    // ldsm base addresses (bytes); kbase selects this warpset's k-half
    const uint32_t kbase = (uint32_t)wset * 1024;   // 512 elems * 2B
    const uint32_t wRowOff = (uint32_t)((wi * 16 + (lane & 15)) * WS + (lane >> 4) * 8) * 2;
    const uint32_t aWh = sb + SM_WHI * 2 + wRowOff + kbase;
    const uint32_t aWl = sb + SM_WLO * 2 + wRowOff + kbase;
    const uint32_t hRowOff = (uint32_t)((wj * 8 + (lane & 7)) * WS + (lane >> 3) * 8) * 2;
    const uint32_t aHh = sb + SM_HHH * 2 + hRowOff + kbase;
    const uint32_t aHl = sb + SM_HHL * 2 + hRowOff + kbase;

    // warp output coordinates in the local 32col x 16batch tile
    const int mrow  = lane >> 2;             // 0..7
    const int nb0   = (lane & 3) * 2;        // 0,2,4,6
    const int lcol0 = wi * 16 + mrow;        // local col, and +8
    const int lb0   = wj * 8 + nb0;          // local batch, and +1
    float* stgw = stg + wset * 16 * 33;

    // combine-phase coordinates (one float2 per thread)
    const int cb   = tid >> 4;               // 0..15 local batch
    const int cc   = (tid & 15) * 2;         // 0..30 local col pair
    const int gb   = bg * 16 + cb;
    const int gc   = cg * 32 + cc;

    volatile unsigned* cbase = (volatile unsigned*)&g_cnt4[bg][0];
    unsigned* myslot = &g_cnt4[bg][(cg & 3) * 8];

    __syncthreads();

    for (int t = 0; t < TT; ++t) {
        const int r = t & 1, w = 1 - r;

        // ---- cp.async: hi group (32KB) committed, then lo group (32KB) ----
#pragma unroll
        for (int s = 0; s < 2; ++s) {
            const __nv_bfloat16* src = &g_hbf[r][s][bg * 16][0];
            uint32_t dst = sb + (uint32_t)(s ? SM_HHL : SM_HHH) * 2;
#pragma unroll
            for (int i = 0; i < 8; ++i) {
                int chunk = tid + i * 256;           // 0..2047
                int row = chunk >> 7, c8 = (chunk & 127) * 8;
                cp16(dst + (uint32_t)(row * WS + c8) * 2, src + row * 1024 + c8);
            }
            CP_COMMIT();
        }

        // prefetch pre for the combine phase (hidden behind waits + MMA)
        const float2 pv = *(const float2*)&g_pre[((size_t)t * BB + gb) * HD + gc];

        float aA0[4], aA1[4], aB0[4], aB1[4], aC0[4], aC1[4];
#pragma unroll
        for (int j = 0; j < 4; ++j) {
            aA0[j] = aA1[j] = aB0[j] = aB1[j] = aC0[j] = aC1[j] = 0.0f;
        }

        // ---- pass 1: A & B terms (need only h-hi; lo still in flight) ----
        CP_WAIT1();
        __syncthreads();

#pragma unroll 4
        for (int ks2 = 0; ks2 < 16; ++ks2) {
            const uint32_t ko = (uint32_t)ks2 * 64;
            uint32_t hh[4];
            ldsm_x4(hh[0], hh[1], hh[2], hh[3], aHh + ko);
            uint32_t wh0[4], wl0[4], wh1[4], wl1[4];
            ldsm_x4(wh0[0], wh0[1], wh0[2], wh0[3], aWh + ko);
            ldsm_x4(wl0[0], wl0[1], wl0[2], wl0[3], aWl + ko);
            ldsm_x4(wh1[0], wh1[1], wh1[2], wh1[3], aWh + ko + 32);
            ldsm_x4(wl1[0], wl1[1], wl1[2], wl1[3], aWl + ko + 32);

            mma16816(aA0, wh0, hh[0], hh[1]);
            mma16816(aB0, wl0, hh[0], hh[1]);
            mma16816(aA1, wh1, hh[2], hh[3]);
            mma16816(aB1, wl1, hh[2], hh[3]);
        }

        // ---- pass 2: C term (needs h-lo) ----
        CP_WAIT0();
        __syncthreads();

#pragma unroll 4
        for (int ks2 = 0; ks2 < 16; ++ks2) {
            const uint32_t ko = (uint32_t)ks2 * 64;
            uint32_t hl[4];
            ldsm_x4(hl[0], hl[1], hl[2], hl[3], aHl + ko);
            uint32_t wh0[4], wh1[4];
            ldsm_x4(wh0[0], wh0[1], wh0[2], wh0[3], aWh + ko);
            ldsm_x4(wh1[0], wh1[1], wh1[2], wh1[3], aWh + ko + 32);

            mma16816(aC0, wh0, hl[0], hl[1]);
            mma16816(aC1, wh1, hl[2], hl[3]);
        }

        // ---- stage this warpset's partial sums ----
#pragma unroll
        for (int j = 0; j < 4; ++j) {
            float cj = ((aA0[j] + aA1[j]) + (aB0[j] + aB1[j])) + (aC0[j] + aC1[j]);
            int bb_ = lb0 + (j & 1);
            int cc_ = lcol0 + (j >> 1) * 8;
            stgw[bb_ * 33 + cc_] = cj;
        }
        __syncthreads();

        // ---- combine: set0 + set1 + pre -> tanh -> split -> store ----
        {
            float v0 = tanh_acc(stg[cb * 33 + cc]     + stg[16 * 33 + cb * 33 + cc]     + pv.x);
            float v1 = tanh_acc(stg[cb * 33 + cc + 1] + stg[16 * 33 + cb * 33 + cc + 1] + pv.y);

            __nv_bfloat16 h0 = __float2bfloat16(v0), h1 = __float2bfloat16(v1);
            __nv_bfloat162 hi2; hi2.x = h0; hi2.y = h1;
            __nv_bfloat162 lo2;
            lo2.x = __float2bfloat16(v0 - __bfloat162float(h0));
            lo2.y = __float2bfloat16(v1 - __bfloat162float(h1));

            *(__nv_bfloat162*)&g_hbf[w][0][gb][gc] = hi2;
            *(__nv_bfloat162*)&g_hbf[w][1][gb][gc] = lo2;

            if (t == TT - 1)
                *(float2*)&g_h[(size_t)gb * HD + gc] = make_float2(v0, v1);
        }

        // ---- barrier: fence + spread RED arrival + volatile sum poll ----
        __threadfence();
        __syncthreads();
        if (tid == 0) {
            atomicAdd(myslot, 1u);                   // result unused -> RED
            const unsigned tgt = 32u * (unsigned)(t + 1);
            unsigned ssum;
            do {
                unsigned a0 = cbase[0];
                unsigned a1 = cbase[8];
                unsigned a2 = cbase[16];
                unsigned a3 = cbase[24];
                ssum = (a0 + a1) + (a2 + a3);
            } while (ssum < tgt);
        }
        __syncthreads();
        __threadfence();
    }
}

// ---------------------------------------------------------------------------
// Phase 3: out[b][o] = h_T[b] . W_out[o] + b_out[o]   grid (64, 4)
// ---------------------------------------------------------------------------
__global__ __launch_bounds__(128) void out_kernel(
    const float* __restrict__ Wout, const float* __restrict__ bout,
    float* __restrict__ out)
{
    __shared__ float hs[HD];
    const int b = blockIdx.x, bo = blockIdx.y, tid = threadIdx.x;
    for (int i = tid; i < HD; i += 128) hs[i] = g_h[(size_t)b * HD + i];
    __syncthreads();
    const int o = bo * 128 + tid;
    const float* w = Wout + (size_t)o * HD;
    float s0 = 0.f, s1 = 0.f, s2 = 0.f, s3 = 0.f;
    for (int k = 0; k < HD; k += 4) {
        float4 wv = *(const float4*)(w + k);
        s0 = fmaf(hs[k + 0], wv.x, s0);
        s1 = fmaf(hs[k + 1], wv.y, s1);
        s2 = fmaf(hs[k + 2], wv.z, s2);
        s3 = fmaf(hs[k + 3], wv.w, s3);
    }
    out[(size_t)b * OD + o] = (s0 + s1) + (s2 + s3) + bout[o];
}

// ---------------------------------------------------------------------------
extern "C" void kernel_launch(void* const* d_in, const int* in_sizes, int n_in,
                              void* d_out, int out_size)
{
    (void)in_sizes; (void)n_in; (void)out_size;
    const float* x    = (const float*)d_in[0];
    const float* Wih  = (const float*)d_in[1];
    const float* Whh  = (const float*)d_in[2];
    const float* bh   = (const float*)d_in[3];
    const float* Wout = (const float*)d_in[4];
    const float* bout = (const float*)d_in[5];
    float* out = (float*)d_out;

    cudaFuncSetAttribute(recur4_kernel,
                         cudaFuncAttributeMaxDynamicSharedMemorySize, R4_SMEM);
    cudaFuncSetAttribute(phase1_mma_kernel,
                         cudaFuncAttributeMaxDynamicSharedMemorySize, P1_SMEM_BYTES);

    init_kernel<<<256, 256>>>();
    split_w_kernel<<<256, 256>>>(Wih);
    split_x_kernel<<<2048, 256>>>(x);

    dim3 g1(8, 1024);                       // (HD/128, M/128) — n-block fastest
    phase1_mma_kernel<<<g1, 256, P1_SMEM_BYTES>>>(bh);

    recur4_kernel<<<128, 256, R4_SMEM>>>(Whh);

    out_kernel<<<dim3(BB, 4), 128>>>(Wout, bout, out);
}

// round 14
// speedup vs baseline: 1.0107x; 1.0107x over previous
#include <cuda_runtime.h>
#include <cuda_bf16.h>
#include <cstdint>
#include <cstddef>

// Problem dims
#define BB   64
#define TT   2048
#define ID   1024
#define HD   1024
#define OD   512

// ---------------------------------------------------------------------------
// Scratch (__device__ globals)
// ---------------------------------------------------------------------------
__device__ float         g_pre[(size_t)TT * BB * HD];        // [t][b][h]  (512 MB)
__device__ __nv_bfloat16 g_abf[(size_t)BB * TT * 2048];      // split X [hi|lo] (512 MB)
__device__ __nv_bfloat16 g_wbf[(size_t)HD * 2048];           // split W_ih [hi|lo] (4 MB)
__device__ __nv_bfloat16 g_hbf[2][2][BB][HD];                // h double-buf, hi/lo (0.5 MB)
__device__ float         g_h[BB * HD];                       // final hidden state
__device__ __align__(128) unsigned g_cnt4[4][32];            // 4 groups; slots 0,8,16,24 used

// ---------------------------------------------------------------------------
// Generic-PTX helpers (safe for compute_103 target: no tcgen05/TMA)
// ---------------------------------------------------------------------------
__device__ __forceinline__ uint32_t smem_to_u32(const void* p) {
    uint32_t a;
    asm("{ .reg .u64 t; cvta.to.shared.u64 t, %1; cvt.u32.u64 %0, t; }"
        : "=r"(a) : "l"(p));
    return a;
}
__device__ __forceinline__ void cp16(uint32_t saddr, const void* g) {
    asm volatile("cp.async.cg.shared.global [%0], [%1], 16;"
                 :: "r"(saddr), "l"(g) : "memory");
}
#define CP_COMMIT() asm volatile("cp.async.commit_group;" ::: "memory")
#define CP_WAIT1()  asm volatile("cp.async.wait_group 1;" ::: "memory")
#define CP_WAIT0()  asm volatile("cp.async.wait_group 0;" ::: "memory")

__device__ __forceinline__ void ldsm_x4(uint32_t& r0, uint32_t& r1,
                                        uint32_t& r2, uint32_t& r3, uint32_t a) {
    asm volatile("ldmatrix.sync.aligned.m8n8.x4.shared.b16 {%0,%1,%2,%3}, [%4];"
                 : "=r"(r0), "=r"(r1), "=r"(r2), "=r"(r3) : "r"(a));
}
__device__ __forceinline__ void mma16816(float* c, const uint32_t* a,
                                         uint32_t b0, uint32_t b1) {
    asm volatile(
        "mma.sync.aligned.m16n8k16.row.col.f32.bf16.bf16.f32 "
        "{%0,%1,%2,%3}, {%4,%5,%6,%7}, {%8,%9}, {%0,%1,%2,%3};"
        : "+f"(c[0]), "+f"(c[1]), "+f"(c[2]), "+f"(c[3])
        : "r"(a[0]), "r"(a[1]), "r"(a[2]), "r"(a[3]), "r"(b0), "r"(b1));
}

// Accurate tanh built from EX2 (avoids tanh.approx under fast-math)
__device__ __forceinline__ float tanh_acc(float x) {
    float ax = fabsf(x);
    float e  = exp2f(ax * 2.885390081777927f);     // e^{2|x|}
    float r  = 1.0f - 2.0f / (e + 1.0f);
    return (x < 0.0f) ? -r : r;
}

// ---------------------------------------------------------------------------
// init: zero h buffer 0 (hi+lo) and the barrier counters.
// ---------------------------------------------------------------------------
__global__ __launch_bounds__(256) void init_kernel() {
    unsigned i = blockIdx.x * 256u + threadIdx.x;          // 0..65535
    ((uint32_t*)g_hbf)[i] = 0u;                            // g_hbf[0][*][*][*]
    if (i < 128) ((unsigned*)g_cnt4)[i] = 0u;
}

// ---------------------------------------------------------------------------
// bf16 2-term split precompute: rows are [hi(1024) | lo(1024)].
// ---------------------------------------------------------------------------
__device__ __forceinline__ void split4(float4 v, ushort4& h, ushort4& l) {
    __nv_bfloat16 hx = __float2bfloat16(v.x);
    __nv_bfloat16 hy = __float2bfloat16(v.y);
    __nv_bfloat16 hz = __float2bfloat16(v.z);
    __nv_bfloat16 hw = __float2bfloat16(v.w);
    h.x = __bfloat16_as_ushort(hx); h.y = __bfloat16_as_ushort(hy);
    h.z = __bfloat16_as_ushort(hz); h.w = __bfloat16_as_ushort(hw);
    l.x = __bfloat16_as_ushort(__float2bfloat16(v.x - __bfloat162float(hx)));
    l.y = __bfloat16_as_ushort(__float2bfloat16(v.y - __bfloat162float(hy)));
    l.z = __bfloat16_as_ushort(__float2bfloat16(v.z - __bfloat162float(hz)));
    l.w = __bfloat16_as_ushort(__float2bfloat16(v.w - __bfloat162float(hw)));
}

__global__ __launch_bounds__(256) void split_x_kernel(const float* __restrict__ X) {
    const size_t n4 = (size_t)BB * TT * ID / 4;
    size_t stride = (size_t)gridDim.x * blockDim.x;
    for (size_t i = (size_t)blockIdx.x * blockDim.x + threadIdx.x; i < n4; i += stride) {
        size_t m  = i >> 8;
        int    k4 = (int)(i & 255);
        float4 v  = ((const float4*)X)[i];
        ushort4 h, l; split4(v, h, l);
        ushort4* row = (ushort4*)(g_abf + m * 2048);
        row[k4] = h; row[256 + k4] = l;
    }
}

__global__ __launch_bounds__(256) void split_w_kernel(const float* __restrict__ W) {
    const size_t n4 = (size_t)HD * ID / 4;
    size_t stride = (size_t)gridDim.x * blockDim.x;
    for (size_t i = (size_t)blockIdx.x * blockDim.x + threadIdx.x; i < n4; i += stride) {
        size_t m  = i >> 8;
        int    k4 = (int)(i & 255);
        float4 v  = ((const float4*)W)[i];
        ushort4 h, l; split4(v, h, l);
        ushort4* row = (ushort4*)(g_wbf + m * 2048);
        row[k4] = h; row[256 + k4] = l;
    }
}

// ---------------------------------------------------------------------------
// Phase 1 (mma.sync bf16): pre = X @ W_ih^T + b_h.
// NEW: k-tile 64 (48 stages instead of 96) — half the syncs/waits, deeper
// ldsm/mma window per stage. 3-stage cp.async pipeline, stride-72 rows
// (144B: +4 banks/row -> conflict-free ldmatrix).
// K'=3072 logical remap into 2048-wide [hi|lo]: A=[hi|hi|lo], W=[hi|lo|hi].
// ---------------------------------------------------------------------------
#define P1_STRIDE 72                                // bf16 elems per row (64+8 pad)
#define P1_NSTG   48
#define P1_BUF    (128 * P1_STRIDE)                 // elems per array per stage
#define P1_SMEM_BYTES (3 * 2 * P1_BUF * 2)          // 110592

__global__ __launch_bounds__(256, 2) void phase1_mma_kernel(const float* __restrict__ bh)
{
    extern __shared__ __nv_bfloat16 p1sm[];

    const int tid  = threadIdx.x;
    const int bn   = blockIdx.x;          // 0..7
    const int bm   = blockIdx.y;          // 0..1023
    const int wid  = tid >> 5, lane = tid & 31;
    const int wm   = wid & 1;
    const int wn   = wid >> 1;

    const __nv_bfloat16* Ag = g_abf + (size_t)(bm * 128) * 2048;
    const __nv_bfloat16* Bg = g_wbf + (size_t)(bn * 128) * 2048;

    const uint32_t sA = smem_to_u32(p1sm);
    const uint32_t sB = sA + 3 * P1_BUF * 2;
    const int lr = tid >> 1;              // 0..127 row
    const int lq = tid & 1;               // half-row (4 chunks of 16B each)

    float acc[4][4][4];
#pragma unroll
    for (int i = 0; i < 4; ++i)
#pragma unroll
        for (int j = 0; j < 4; ++j)
#pragma unroll
            for (int k = 0; k < 4; ++k) acc[i][j][k] = 0.0f;

// stage kt in [0,48): A k-offset = ((kt<16)?kt:kt-16)*64  -> [hi|hi|lo]
//                     W k-offset = ((kt<32)?kt:kt-32)*64  -> [hi|lo|hi]
#define LOAD_STAGE(kt, buf) do {                                                   \
    int aoff = (((kt) < 16) ? (kt) : ((kt) - 16)) * 64;                            \
    int woff = (((kt) < 32) ? (kt) : ((kt) - 32)) * 64;                            \
    const __nv_bfloat16* ag = Ag + (size_t)lr * 2048 + aoff + lq * 32;             \
    const __nv_bfloat16* bg = Bg + (size_t)lr * 2048 + woff + lq * 32;             \
    uint32_t da = sA + (uint32_t)((buf) * P1_BUF + lr * P1_STRIDE + lq * 32) * 2;  \
    uint32_t db = sB + (uint32_t)((buf) * P1_BUF + lr * P1_STRIDE + lq * 32) * 2;  \
    cp16(da,      ag);      cp16(da + 16, ag + 8);                                 \
    cp16(da + 32, ag + 16); cp16(da + 48, ag + 24);                                \
    cp16(db,      bg);      cp16(db + 16, bg + 8);                                 \
    cp16(db + 32, bg + 16); cp16(db + 48, bg + 24);                                \
} while (0)

    LOAD_STAGE(0, 0); CP_COMMIT();
    LOAD_STAGE(1, 1); CP_COMMIT();

    const int lrow  = lane & 15;
    const int lhalf = lane >> 4;

    int buf = 0;
    for (int kt = 0; kt < P1_NSTG; ++kt) {
        if (kt < P1_NSTG - 1) { CP_WAIT1(); } else { CP_WAIT0(); }
        __syncthreads();

        if (kt + 2 < P1_NSTG) {
            int bld = buf + 2; if (bld >= 3) bld -= 3;
            LOAD_STAGE(kt + 2, bld); CP_COMMIT();
        }

        const uint32_t abase = sA + (uint32_t)(buf * P1_BUF) * 2;
        const uint32_t bbase = sB + (uint32_t)(buf * P1_BUF) * 2;

#pragma unroll
        for (int ks = 0; ks < 4; ++ks) {
            uint32_t a[4][4];
#pragma unroll
            for (int mt = 0; mt < 4; ++mt) {
                uint32_t ad = abase +
                    (uint32_t)((wm * 64 + mt * 16 + lrow) * P1_STRIDE + ks * 16 + lhalf * 8) * 2;
                ldsm_x4(a[mt][0], a[mt][1], a[mt][2], a[mt][3], ad);
            }
            uint32_t bf[2][4];
#pragma unroll
            for (int bp = 0; bp < 2; ++bp) {
                uint32_t bd = bbase +
                    (uint32_t)((wn * 32 + bp * 16 + lrow) * P1_STRIDE + ks * 16 + lhalf * 8) * 2;
                ldsm_x4(bf[bp][0], bf[bp][1], bf[bp][2], bf[bp][3], bd);
            }
#pragma unroll
            for (int mt = 0; mt < 4; ++mt)
#pragma unroll
                for (int nt = 0; nt < 4; ++nt)
                    mma16816(acc[mt][nt], a[mt],
                             bf[nt >> 1][nt & 1], bf[nt >> 1][(nt & 1) + 2]);
        }

        if (++buf == 3) buf = 0;
    }
#undef LOAD_STAGE

    const int col0 = bn * 128 + wn * 32;
#pragma unroll
    for (int mt = 0; mt < 4; ++mt) {
#pragma unroll
        for (int half = 0; half < 2; ++half) {
            int m  = bm * 128 + wm * 64 + mt * 16 + (lane >> 2) + half * 8;
            int b_ = m >> 11;
            int t_ = m & (TT - 1);
            float* orow = g_pre + ((size_t)t_ * BB + b_) * HD;
#pragma unroll
            for (int nt = 0; nt < 4; ++nt) {
                int c = col0 + nt * 8 + (lane & 3) * 2;
                float2 v;
                v.x = acc[mt][nt][half * 2 + 0] + __ldg(bh + c);
                v.y = acc[mt][nt][half * 2 + 1] + __ldg(bh + c + 1);
                *(float2*)(orow + c) = v;
            }
        }
    }
}

// ---------------------------------------------------------------------------
// Phase 2: persistent recurrence (R12 EXACT — best-known configuration).
// 128 CTAs = 4 batch-groups(16 rows) x 32 col-groups(32 cols), 256 threads.
// 8 warps = 2 warpsets: set0 k[0,512), set1 k[512,1024).
// Barrier: fence + atomicAdd to 4 spread counters (cg&3, 32B apart) +
// volatile 4-load sum poll + trailing fence.
// ---------------------------------------------------------------------------
#define WS        1032                       // bf16 elems per smem row (129*16B)
#define SM_WHI    0
#define SM_WLO    (32 * WS)
#define SM_HHH    (64 * WS)
#define SM_HHL    (80 * WS)
#define SM_STGF   (96 * WS)                  // float staging [2][16][33] after this
#define R4_SMEM   (96 * WS * 2 + 2 * 16 * 33 * 4)   // 202368

__global__ __launch_bounds__(256, 1) void recur4_kernel(const float* __restrict__ Whh)
{
    extern __shared__ __nv_bfloat16 sm[];
    float* stg = (float*)&sm[SM_STGF];       // [2][16][33]
    const int tid  = threadIdx.x;
    const int lane = tid & 31, wid = tid >> 5;
    const int wset = wid >> 2;               // k-half
    const int w4   = wid & 3;
    const int wi   = w4 & 1;                 // col half (16 cols)
    const int wj   = w4 >> 1;                // batch half (8 rows)
    const int bg   = blockIdx.x >> 5;        // 0..3
    const int cg   = blockIdx.x & 31;        // 0..31
    const uint32_t sb = smem_to_u32(sm);

    // ---- persistent W_hh slice [32 cols][1024 k], split hi/lo ----
    for (int e = tid; e < 32 * 1024; e += 256) {
        int n = e >> 10, k = e & 1023;
        float v = Whh[(size_t)(cg * 32 + n) * HD + k];
        __nv_bfloat16 h = __float2bfloat16(v);
        sm[SM_WHI + n * WS + k] = h;
        sm[SM_WLO + n * WS + k] = __float2bfloat16(v - __bfloat162float(h));
    }

    // ldsm base addresses (bytes); kbase selects this warpset's k-half
    const uint32_t kbase = (uint32_t)wset * 1024;   // 512 elems * 2B
    const uint32_t wRowOff = (uint32_t)((wi * 16 + (lane & 15)) * WS + (lane >> 4) * 8) * 2;
    const uint32_t aWh = sb + SM_WHI * 2 + wRowOff + kbase;
    const uint32_t aWl = sb + SM_WLO * 2 + wRowOff + kbase;
    const uint32_t hRowOff = (uint32_t)((wj * 8 + (lane & 7)) * WS + (lane >> 3) * 8) * 2;
    const uint32_t aHh = sb + SM_HHH * 2 + hRowOff + kbase;
    const uint32_t aHl = sb + SM_HHL * 2 + hRowOff + kbase;

    // warp output coordinates in the local 32col x 16batch tile
    const int mrow  = lane >> 2;             // 0..7
    const int nb0   = (lane & 3) * 2;        // 0,2,4,6
    const int lcol0 = wi * 16 + mrow;        // local col, and +8
    const int lb0   = wj * 8 + nb0;          // local batch, and +1
    float* stgw = stg + wset * 16 * 33;

    // combine-phase coordinates (one float2 per thread)
    const int cb   = tid >> 4;               // 0..15 local batch
    const int cc   = (tid & 15) * 2;         // 0..30 local col pair
    const int gb   = bg * 16 + cb;
    const int gc   = cg * 32 + cc;

    volatile unsigned* cbase = (volatile unsigned*)&g_cnt4[bg][0];
    unsigned* myslot = &g_cnt4[bg][(cg & 3) * 8];

    __syncthreads();

    for (int t = 0; t < TT; ++t) {
        const int r = t & 1, w = 1 - r;

        // ---- load h slice (hi+lo) into smem via cp.async (256 threads) ----
#pragma unroll
        for (int s = 0; s < 2; ++s) {
            const __nv_bfloat16* src = &g_hbf[r][s][bg * 16][0];
            uint32_t dst = sb + (uint32_t)(s ? SM_HHL : SM_HHH) * 2;
#pragma unroll
            for (int i = 0; i < 8; ++i) {
                int chunk = tid + i * 256;           // 0..2047
                int row = chunk >> 7, c8 = (chunk & 127) * 8;
                cp16(dst + (uint32_t)(row * WS + c8) * 2, src + row * 1024 + c8);
            }
        }
        CP_COMMIT();

        // prefetch pre for the combine phase (hidden behind cp wait + MMA)
        const float2 pv = *(const float2*)&g_pre[((size_t)t * BB + gb) * HD + gc];

        CP_WAIT0();
        __syncthreads();

        // ---- fused 3-term split GEMM over this warpset's k-half ----
        float aA0[4], aA1[4], aB0[4], aB1[4], aC0[4], aC1[4];
#pragma unroll
        for (int j = 0; j < 4; ++j) {
            aA0[j] = aA1[j] = aB0[j] = aB1[j] = aC0[j] = aC1[j] = 0.0f;
        }

#pragma unroll 4
        for (int ks2 = 0; ks2 < 16; ++ks2) {
            const uint32_t ko = (uint32_t)ks2 * 64;
            uint32_t hh[4], hl[4];
            ldsm_x4(hh[0], hh[1], hh[2], hh[3], aHh + ko);
            ldsm_x4(hl[0], hl[1], hl[2], hl[3], aHl + ko);
            uint32_t wh0[4], wl0[4], wh1[4], wl1[4];
            ldsm_x4(wh0[0], wh0[1], wh0[2], wh0[3], aWh + ko);
            ldsm_x4(wl0[0], wl0[1], wl0[2], wl0[3], aWl + ko);
            ldsm_x4(wh1[0], wh1[1], wh1[2], wh1[3], aWh + ko + 32);
            ldsm_x4(wl1[0], wl1[1], wl1[2], wl1[3], aWl + ko + 32);

            mma16816(aA0, wh0, hh[0], hh[1]);
            mma16816(aB0, wl0, hh[0], hh[1]);
            mma16816(aC0, wh0, hl[0], hl[1]);
            mma16816(aA1, wh1, hh[2], hh[3]);
            mma16816(aB1, wl1, hh[2], hh[3]);
            mma16816(aC1, wh1, hl[2], hl[3]);
        }

        // ---- stage this warpset's partial sums ----
#pragma unroll
        for (int j = 0; j < 4; ++j) {
            float cj = ((aA0[j] + aA1[j]) + (aB0[j] + aB1[j])) + (aC0[j] + aC1[j]);
            int bb_ = lb0 + (j & 1);
            int cc_ = lcol0 + (j >> 1) * 8;
            stgw[bb_ * 33 + cc_] = cj;
        }
        __syncthreads();

        // ---- combine: set0 + set1 + pre -> tanh -> split -> store ----
        {
            float v0 = tanh_acc(stg[cb * 33 + cc]     + stg[16 * 33 + cb * 33 + cc]     + pv.x);
            float v1 = tanh_acc(stg[cb * 33 + cc + 1] + stg[16 * 33 + cb * 33 + cc + 1] + pv.y);

            __nv_bfloat16 h0 = __float2bfloat16(v0), h1 = __float2bfloat16(v1);
            __nv_bfloat162 hi2; hi2.x = h0; hi2.y = h1;
            __nv_bfloat162 lo2;
            lo2.x = __float2bfloat16(v0 - __bfloat162float(h0));
            lo2.y = __float2bfloat16(v1 - __bfloat162float(h1));

            *(__nv_bfloat162*)&g_hbf[w][0][gb][gc] = hi2;
            *(__nv_bfloat162*)&g_hbf[w][1][gb][gc] = lo2;

            if (t == TT - 1)
                *(float2*)&g_h[(size_t)gb * HD + gc] = make_float2(v0, v1);
        }

        // ---- barrier: fence + spread RED arrival + volatile sum poll ----
        __threadfence();
        __syncthreads();
        if (tid == 0) {
            atomicAdd(myslot, 1u);                   // result unused -> RED
            const unsigned tgt = 32u * (unsigned)(t + 1);
            unsigned ssum;
            do {
                unsigned a0 = cbase[0];
                unsigned a1 = cbase[8];
                unsigned a2 = cbase[16];
                unsigned a3 = cbase[24];
                ssum = (a0 + a1) + (a2 + a3);
            } while (ssum < tgt);
        }
        __syncthreads();
        __threadfence();
    }
}

// ---------------------------------------------------------------------------
// Phase 3: out[b][o] = h_T[b] . W_out[o] + b_out[o]   grid (64, 4)
// ---------------------------------------------------------------------------
__global__ __launch_bounds__(128) void out_kernel(
    const float* __restrict__ Wout, const float* __restrict__ bout,
    float* __restrict__ out)
{
    __shared__ float hs[HD];
    const int b = blockIdx.x, bo = blockIdx.y, tid = threadIdx.x;
    for (int i = tid; i < HD; i += 128) hs[i] = g_h[(size_t)b * HD + i];
    __syncthreads();
    const int o = bo * 128 + tid;
    const float* w = Wout + (size_t)o * HD;
    float s0 = 0.f, s1 = 0.f, s2 = 0.f, s3 = 0.f;
    for (int k = 0; k < HD; k += 4) {
        float4 wv = *(const float4*)(w + k);
        s0 = fmaf(hs[k + 0], wv.x, s0);
        s1 = fmaf(hs[k + 1], wv.y, s1);
        s2 = fmaf(hs[k + 2], wv.z, s2);
        s3 = fmaf(hs[k + 3], wv.w, s3);
    }
    out[(size_t)b * OD + o] = (s0 + s1) + (s2 + s3) + bout[o];
}

// ---------------------------------------------------------------------------
extern "C" void kernel_launch(void* const* d_in, const int* in_sizes, int n_in,
                              void* d_out, int out_size)
{
    (void)in_sizes; (void)n_in; (void)out_size;
    const float* x    = (const float*)d_in[0];
    const float* Wih  = (const float*)d_in[1];
    const float* Whh  = (const float*)d_in[2];
    const float* bh   = (const float*)d_in[3];
    const float* Wout = (const float*)d_in[4];
    const float* bout = (const float*)d_in[5];
    float* out = (float*)d_out;

    cudaFuncSetAttribute(recur4_kernel,
                         cudaFuncAttributeMaxDynamicSharedMemorySize, R4_SMEM);
    cudaFuncSetAttribute(phase1_mma_kernel,
                         cudaFuncAttributeMaxDynamicSharedMemorySize, P1_SMEM_BYTES);

    init_kernel<<<256, 256>>>();
    split_w_kernel<<<256, 256>>>(Wih);
    split_x_kernel<<<2048, 256>>>(x);

    dim3 g1(8, 1024);                       // (HD/128, M/128) — n-block fastest
    phase1_mma_kernel<<<g1, 256, P1_SMEM_BYTES>>>(bh);

    recur4_kernel<<<128, 256, R4_SMEM>>>(Whh);

    out_kernel<<<dim3(BB, 4), 128>>>(Wout, bout, out);
}

// round 15
// speedup vs baseline: 1.1106x; 1.0989x over previous
#include <cuda_runtime.h>
#include <cuda_bf16.h>
#include <cstdint>
#include <cstddef>

// Problem dims
#define BB   64
#define TT   2048
#define ID   1024
#define HD   1024
#define OD   512

// ---------------------------------------------------------------------------
// Scratch (__device__ globals)
// ---------------------------------------------------------------------------
__device__ float         g_pre[(size_t)TT * BB * HD];        // [t][b][h]  (512 MB)
__device__ __nv_bfloat16 g_abf[(size_t)BB * TT * 2048];      // split X [hi|lo] (512 MB)
__device__ __nv_bfloat16 g_wbf[(size_t)HD * 2048];           // split W_ih [hi|lo] (4 MB)
__device__ __nv_bfloat16 g_hbf[2][2][BB][HD];                // h double-buf, hi/lo (0.5 MB)
__device__ float         g_h[BB * HD];                       // final hidden state
__device__ __align__(128) unsigned g_cnt4[4][32];            // 4 groups; slots 0,8,16,24 used

// ---------------------------------------------------------------------------
// Generic-PTX helpers (safe for compute_103 target: no tcgen05/TMA)
// ---------------------------------------------------------------------------
__device__ __forceinline__ uint32_t smem_to_u32(const void* p) {
    uint32_t a;
    asm("{ .reg .u64 t; cvta.to.shared.u64 t, %1; cvt.u32.u64 %0, t; }"
        : "=r"(a) : "l"(p));
    return a;
}
__device__ __forceinline__ void cp16(uint32_t saddr, const void* g) {
    asm volatile("cp.async.cg.shared.global [%0], [%1], 16;"
                 :: "r"(saddr), "l"(g) : "memory");
}
#define CP_COMMIT() asm volatile("cp.async.commit_group;" ::: "memory")
#define CP_WAIT1()  asm volatile("cp.async.wait_group 1;" ::: "memory")
#define CP_WAIT0()  asm volatile("cp.async.wait_group 0;" ::: "memory")

__device__ __forceinline__ void ldsm_x4(uint32_t& r0, uint32_t& r1,
                                        uint32_t& r2, uint32_t& r3, uint32_t a) {
    asm volatile("ldmatrix.sync.aligned.m8n8.x4.shared.b16 {%0,%1,%2,%3}, [%4];"
                 : "=r"(r0), "=r"(r1), "=r"(r2), "=r"(r3) : "r"(a));
}
__device__ __forceinline__ void mma16816(float* c, const uint32_t* a,
                                         uint32_t b0, uint32_t b1) {
    asm volatile(
        "mma.sync.aligned.m16n8k16.row.col.f32.bf16.bf16.f32 "
        "{%0,%1,%2,%3}, {%4,%5,%6,%7}, {%8,%9}, {%0,%1,%2,%3};"
        : "+f"(c[0]), "+f"(c[1]), "+f"(c[2]), "+f"(c[3])
        : "r"(a[0]), "r"(a[1]), "r"(a[2]), "r"(a[3]), "r"(b0), "r"(b1));
}

// Accurate tanh built from EX2 (avoids tanh.approx under fast-math)
__device__ __forceinline__ float tanh_acc(float x) {
    float ax = fabsf(x);
    float e  = exp2f(ax * 2.885390081777927f);     // e^{2|x|}
    float r  = 1.0f - 2.0f / (e + 1.0f);
    return (x < 0.0f) ? -r : r;
}

// ---------------------------------------------------------------------------
// init: zero h buffer 0 (hi+lo) and the barrier counters.
// ---------------------------------------------------------------------------
__global__ __launch_bounds__(256) void init_kernel() {
    unsigned i = blockIdx.x * 256u + threadIdx.x;          // 0..65535
    ((uint32_t*)g_hbf)[i] = 0u;                            // g_hbf[0][*][*][*]
    if (i < 128) ((unsigned*)g_cnt4)[i] = 0u;
}

// ---------------------------------------------------------------------------
// bf16 2-term split precompute: rows are [hi(1024) | lo(1024)].
// ---------------------------------------------------------------------------
__device__ __forceinline__ void split4(float4 v, ushort4& h, ushort4& l) {
    __nv_bfloat16 hx = __float2bfloat16(v.x);
    __nv_bfloat16 hy = __float2bfloat16(v.y);
    __nv_bfloat16 hz = __float2bfloat16(v.z);
    __nv_bfloat16 hw = __float2bfloat16(v.w);
    h.x = __bfloat16_as_ushort(hx); h.y = __bfloat16_as_ushort(hy);
    h.z = __bfloat16_as_ushort(hz); h.w = __bfloat16_as_ushort(hw);
    l.x = __bfloat16_as_ushort(__float2bfloat16(v.x - __bfloat162float(hx)));
    l.y = __bfloat16_as_ushort(__float2bfloat16(v.y - __bfloat162float(hy)));
    l.z = __bfloat16_as_ushort(__float2bfloat16(v.z - __bfloat162float(hz)));
    l.w = __bfloat16_as_ushort(__float2bfloat16(v.w - __bfloat162float(hw)));
}

__global__ __launch_bounds__(256) void split_x_kernel(const float* __restrict__ X) {
    const size_t n4 = (size_t)BB * TT * ID / 4;
    size_t stride = (size_t)gridDim.x * blockDim.x;
    for (size_t i = (size_t)blockIdx.x * blockDim.x + threadIdx.x; i < n4; i += stride) {
        size_t m  = i >> 8;
        int    k4 = (int)(i & 255);
        float4 v  = ((const float4*)X)[i];
        ushort4 h, l; split4(v, h, l);
        ushort4* row = (ushort4*)(g_abf + m * 2048);
        row[k4] = h; row[256 + k4] = l;
    }
}

__global__ __launch_bounds__(256) void split_w_kernel(const float* __restrict__ W) {
    const size_t n4 = (size_t)HD * ID / 4;
    size_t stride = (size_t)gridDim.x * blockDim.x;
    for (size_t i = (size_t)blockIdx.x * blockDim.x + threadIdx.x; i < n4; i += stride) {
        size_t m  = i >> 8;
        int    k4 = (int)(i & 255);
        float4 v  = ((const float4*)W)[i];
        ushort4 h, l; split4(v, h, l);
        ushort4* row = (ushort4*)(g_wbf + m * 2048);
        row[k4] = h; row[256 + k4] = l;
    }
}

// ---------------------------------------------------------------------------
// Phase 1 (mma.sync bf16): pre = X @ W_ih^T + b_h.
// R12 EXACT: k-tile 32 (96 stages), stride-40 rows, 3-stage cp.async
// pipeline, one __syncthreads per stage.
// K'=3072 logical remap into 2048-wide [hi|lo]: A=[hi|hi|lo], W=[hi|lo|hi].
// ---------------------------------------------------------------------------
#define P1_STRIDE 40
#define P1_NSTG   96
#define P1_BUF    (128 * P1_STRIDE)                 // elems per array per stage
#define P1_SMEM_BYTES (3 * 2 * P1_BUF * 2)          // 61440

__global__ __launch_bounds__(256, 2) void phase1_mma_kernel(const float* __restrict__ bh)
{
    extern __shared__ __nv_bfloat16 p1sm[];

    const int tid  = threadIdx.x;
    const int bn   = blockIdx.x;          // 0..7
    const int bm   = blockIdx.y;          // 0..1023
    const int wid  = tid >> 5, lane = tid & 31;
    const int wm   = wid & 1;
    const int wn   = wid >> 1;

    const __nv_bfloat16* Ag = g_abf + (size_t)(bm * 128) * 2048;
    const __nv_bfloat16* Bg = g_wbf + (size_t)(bn * 128) * 2048;

    const uint32_t sA = smem_to_u32(p1sm);
    const uint32_t sB = sA + 3 * P1_BUF * 2;
    const int lr = tid >> 2, lq = tid & 3;

    float acc[4][4][4];
#pragma unroll
    for (int i = 0; i < 4; ++i)
#pragma unroll
        for (int j = 0; j < 4; ++j)
#pragma unroll
            for (int k = 0; k < 4; ++k) acc[i][j][k] = 0.0f;

#define LOAD_STAGE(kt, buf) do {                                                  \
    int aoff = (((kt) < 32) ? (kt) : ((kt) - 32)) * 32;                           \
    int woff = (((kt) < 64) ? (kt) : ((kt) - 64)) * 32;                           \
    const __nv_bfloat16* ag = Ag + (size_t)lr * 2048 + aoff + lq * 8;             \
    const __nv_bfloat16* bg = Bg + (size_t)lr * 2048 + woff + lq * 8;             \
    uint32_t da = sA + (uint32_t)((buf) * P1_BUF + lr * P1_STRIDE + lq * 8) * 2;  \
    uint32_t db = sB + (uint32_t)((buf) * P1_BUF + lr * P1_STRIDE + lq * 8) * 2;  \
    cp16(da, ag); cp16(da + 64 * P1_STRIDE * 2, ag + (size_t)64 * 2048);          \
    cp16(db, bg); cp16(db + 64 * P1_STRIDE * 2, bg + (size_t)64 * 2048);          \
} while (0)

    LOAD_STAGE(0, 0); CP_COMMIT();
    LOAD_STAGE(1, 1); CP_COMMIT();

    const int lrow  = lane & 15;
    const int lhalf = lane >> 4;

    int buf = 0;
    for (int kt = 0; kt < P1_NSTG; ++kt) {
        if (kt < P1_NSTG - 1) { CP_WAIT1(); } else { CP_WAIT0(); }
        __syncthreads();

        if (kt + 2 < P1_NSTG) {
            int bld = buf + 2; if (bld >= 3) bld -= 3;
            LOAD_STAGE(kt + 2, bld); CP_COMMIT();
        }

        const uint32_t abase = sA + (uint32_t)(buf * P1_BUF) * 2;
        const uint32_t bbase = sB + (uint32_t)(buf * P1_BUF) * 2;

#pragma unroll
        for (int ks = 0; ks < 2; ++ks) {
            uint32_t a[4][4];
#pragma unroll
            for (int mt = 0; mt < 4; ++mt) {
                uint32_t ad = abase +
                    (uint32_t)((wm * 64 + mt * 16 + lrow) * P1_STRIDE + ks * 16 + lhalf * 8) * 2;
                ldsm_x4(a[mt][0], a[mt][1], a[mt][2], a[mt][3], ad);
            }
            uint32_t bf[2][4];
#pragma unroll
            for (int bp = 0; bp < 2; ++bp) {
                uint32_t bd = bbase +
                    (uint32_t)((wn * 32 + bp * 16 + lrow) * P1_STRIDE + ks * 16 + lhalf * 8) * 2;
                ldsm_x4(bf[bp][0], bf[bp][1], bf[bp][2], bf[bp][3], bd);
            }
#pragma unroll
            for (int mt = 0; mt < 4; ++mt)
#pragma unroll
                for (int nt = 0; nt < 4; ++nt)
                    mma16816(acc[mt][nt], a[mt],
                             bf[nt >> 1][nt & 1], bf[nt >> 1][(nt & 1) + 2]);
        }

        if (++buf == 3) buf = 0;
    }
#undef LOAD_STAGE

    const int col0 = bn * 128 + wn * 32;
#pragma unroll
    for (int mt = 0; mt < 4; ++mt) {
#pragma unroll
        for (int half = 0; half < 2; ++half) {
            int m  = bm * 128 + wm * 64 + mt * 16 + (lane >> 2) + half * 8;
            int b_ = m >> 11;
            int t_ = m & (TT - 1);
            float* orow = g_pre + ((size_t)t_ * BB + b_) * HD;
#pragma unroll
            for (int nt = 0; nt < 4; ++nt) {
                int c = col0 + nt * 8 + (lane & 3) * 2;
                float2 v;
                v.x = acc[mt][nt][half * 2 + 0] + __ldg(bh + c);
                v.y = acc[mt][nt][half * 2 + 1] + __ldg(bh + c + 1);
                *(float2*)(orow + c) = v;
            }
        }
    }
}

// ---------------------------------------------------------------------------
// Phase 2: persistent recurrence (R12 structure; ONLY change: the two
// __threadfence() calls move inside the tid==0 branch — PTX fences are
// cumulative, so tid0's fence after __syncthreads publishes ALL threads'
// h-stores before the RED arrival (same construction as cooperative-groups
// grid.sync), saving 2x255 MEMBARs per CTA per step).
// 128 CTAs = 4 batch-groups(16 rows) x 32 col-groups(32 cols), 256 threads.
// 8 warps = 2 warpsets: set0 k[0,512), set1 k[512,1024).
// ---------------------------------------------------------------------------
#define WS        1032                       // bf16 elems per smem row (129*16B)
#define SM_WHI    0
#define SM_WLO    (32 * WS)
#define SM_HHH    (64 * WS)
#define SM_HHL    (80 * WS)
#define SM_STGF   (96 * WS)                  // float staging [2][16][33] after this
#define R4_SMEM   (96 * WS * 2 + 2 * 16 * 33 * 4)   // 202368

__global__ __launch_bounds__(256, 1) void recur4_kernel(const float* __restrict__ Whh)
{
    extern __shared__ __nv_bfloat16 sm[];
    float* stg = (float*)&sm[SM_STGF];       // [2][16][33]
    const int tid  = threadIdx.x;
    const int lane = tid & 31, wid = tid >> 5;
    const int wset = wid >> 2;               // k-half
    const int w4   = wid & 3;
    const int wi   = w4 & 1;                 // col half (16 cols)
    const int wj   = w4 >> 1;                // batch half (8 rows)
    const int bg   = blockIdx.x >> 5;        // 0..3
    const int cg   = blockIdx.x & 31;        // 0..31
    const uint32_t sb = smem_to_u32(sm);

    // ---- persistent W_hh slice [32 cols][1024 k], split hi/lo ----
    for (int e = tid; e < 32 * 1024; e += 256) {
        int n = e >> 10, k = e & 1023;
        float v = Whh[(size_t)(cg * 32 + n) * HD + k];
        __nv_bfloat16 h = __float2bfloat16(v);
        sm[SM_WHI + n * WS + k] = h;
        sm[SM_WLO + n * WS + k] = __float2bfloat16(v - __bfloat162float(h));
    }

    // ldsm base addresses (bytes); kbase selects this warpset's k-half
    const uint32_t kbase = (uint32_t)wset * 1024;   // 512 elems * 2B
    const uint32_t wRowOff = (uint32_t)((wi * 16 + (lane & 15)) * WS + (lane >> 4) * 8) * 2;
    const uint32_t aWh = sb + SM_WHI * 2 + wRowOff + kbase;
    const uint32_t aWl = sb + SM_WLO * 2 + wRowOff + kbase;
    const uint32_t hRowOff = (uint32_t)((wj * 8 + (lane & 7)) * WS + (lane >> 3) * 8) * 2;
    const uint32_t aHh = sb + SM_HHH * 2 + hRowOff + kbase;
    const uint32_t aHl = sb + SM_HHL * 2 + hRowOff + kbase;

    // warp output coordinates in the local 32col x 16batch tile
    const int mrow  = lane >> 2;             // 0..7
    const int nb0   = (lane & 3) * 2;        // 0,2,4,6
    const int lcol0 = wi * 16 + mrow;        // local col, and +8
    const int lb0   = wj * 8 + nb0;          // local batch, and +1
    float* stgw = stg + wset * 16 * 33;

    // combine-phase coordinates (one float2 per thread)
    const int cb   = tid >> 4;               // 0..15 local batch
    const int cc   = (tid & 15) * 2;         // 0..30 local col pair
    const int gb   = bg * 16 + cb;
    const int gc   = cg * 32 + cc;

    volatile unsigned* cbase = (volatile unsigned*)&g_cnt4[bg][0];
    unsigned* myslot = &g_cnt4[bg][(cg & 3) * 8];

    __syncthreads();

    for (int t = 0; t < TT; ++t) {
        const int r = t & 1, w = 1 - r;

        // ---- load h slice (hi+lo) into smem via cp.async (256 threads) ----
#pragma unroll
        for (int s = 0; s < 2; ++s) {
            const __nv_bfloat16* src = &g_hbf[r][s][bg * 16][0];
            uint32_t dst = sb + (uint32_t)(s ? SM_HHL : SM_HHH) * 2;
#pragma unroll
            for (int i = 0; i < 8; ++i) {
                int chunk = tid + i * 256;           // 0..2047
                int row = chunk >> 7, c8 = (chunk & 127) * 8;
                cp16(dst + (uint32_t)(row * WS + c8) * 2, src + row * 1024 + c8);
            }
        }
        CP_COMMIT();

        // prefetch pre for the combine phase (hidden behind cp wait + MMA)
        const float2 pv = *(const float2*)&g_pre[((size_t)t * BB + gb) * HD + gc];

        CP_WAIT0();
        __syncthreads();

        // ---- fused 3-term split GEMM over this warpset's k-half ----
        float aA0[4], aA1[4], aB0[4], aB1[4], aC0[4], aC1[4];
#pragma unroll
        for (int j = 0; j < 4; ++j) {
            aA0[j] = aA1[j] = aB0[j] = aB1[j] = aC0[j] = aC1[j] = 0.0f;
        }

#pragma unroll 4
        for (int ks2 = 0; ks2 < 16; ++ks2) {
            const uint32_t ko = (uint32_t)ks2 * 64;
            uint32_t hh[4], hl[4];
            ldsm_x4(hh[0], hh[1], hh[2], hh[3], aHh + ko);
            ldsm_x4(hl[0], hl[1], hl[2], hl[3], aHl + ko);
            uint32_t wh0[4], wl0[4], wh1[4], wl1[4];
            ldsm_x4(wh0[0], wh0[1], wh0[2], wh0[3], aWh + ko);
            ldsm_x4(wl0[0], wl0[1], wl0[2], wl0[3], aWl + ko);
            ldsm_x4(wh1[0], wh1[1], wh1[2], wh1[3], aWh + ko + 32);
            ldsm_x4(wl1[0], wl1[1], wl1[2], wl1[3], aWl + ko + 32);

            mma16816(aA0, wh0, hh[0], hh[1]);
            mma16816(aB0, wl0, hh[0], hh[1]);
            mma16816(aC0, wh0, hl[0], hl[1]);
            mma16816(aA1, wh1, hh[2], hh[3]);
            mma16816(aB1, wl1, hh[2], hh[3]);
            mma16816(aC1, wh1, hl[2], hl[3]);
        }

        // ---- stage this warpset's partial sums ----
#pragma unroll
        for (int j = 0; j < 4; ++j) {
            float cj = ((aA0[j] + aA1[j]) + (aB0[j] + aB1[j])) + (aC0[j] + aC1[j]);
            int bb_ = lb0 + (j & 1);
            int cc_ = lcol0 + (j >> 1) * 8;
            stgw[bb_ * 33 + cc_] = cj;
        }
        __syncthreads();

        // ---- combine: set0 + set1 + pre -> tanh -> split -> store ----
        {
            float v0 = tanh_acc(stg[cb * 33 + cc]     + stg[16 * 33 + cb * 33 + cc]     + pv.x);
            float v1 = tanh_acc(stg[cb * 33 + cc + 1] + stg[16 * 33 + cb * 33 + cc + 1] + pv.y);

            __nv_bfloat16 h0 = __float2bfloat16(v0), h1 = __float2bfloat16(v1);
            __nv_bfloat162 hi2; hi2.x = h0; hi2.y = h1;
            __nv_bfloat162 lo2;
            lo2.x = __float2bfloat16(v0 - __bfloat162float(h0));
            lo2.y = __float2bfloat16(v1 - __bfloat162float(h1));

            *(__nv_bfloat162*)&g_hbf[w][0][gb][gc] = hi2;
            *(__nv_bfloat162*)&g_hbf[w][1][gb][gc] = lo2;

            if (t == TT - 1)
                *(float2*)&g_h[(size_t)gb * HD + gc] = make_float2(v0, v1);
        }

        // ---- barrier: tid0-only cumulative fences + spread RED + poll ----
        __syncthreads();                      // all h stores happen-before tid0
        if (tid == 0) {
            __threadfence();                  // cumulative: publishes ALL h stores
            atomicAdd(myslot, 1u);            // result unused -> RED
            const unsigned tgt = 32u * (unsigned)(t + 1);
            unsigned ssum;
            do {
                unsigned a0 = cbase[0];
                unsigned a1 = cbase[8];
                unsigned a2 = cbase[16];
                unsigned a3 = cbase[24];
                ssum = (a0 + a1) + (a2 + a3);
            } while (ssum < tgt);
            __threadfence();                  // cumulative: orders later h loads
        }
        __syncthreads();
    }
}

// ---------------------------------------------------------------------------
// Phase 3: out[b][o] = h_T[b] . W_out[o] + b_out[o]   grid (64, 4)
// ---------------------------------------------------------------------------
__global__ __launch_bounds__(128) void out_kernel(
    const float* __restrict__ Wout, const float* __restrict__ bout,
    float* __restrict__ out)
{
    __shared__ float hs[HD];
    const int b = blockIdx.x, bo = blockIdx.y, tid = threadIdx.x;
    for (int i = tid; i < HD; i += 128) hs[i] = g_h[(size_t)b * HD + i];
    __syncthreads();
    const int o = bo * 128 + tid;
    const float* w = Wout + (size_t)o * HD;
    float s0 = 0.f, s1 = 0.f, s2 = 0.f, s3 = 0.f;
    for (int k = 0; k < HD; k += 4) {
        float4 wv = *(const float4*)(w + k);
        s0 = fmaf(hs[k + 0], wv.x, s0);
        s1 = fmaf(hs[k + 1], wv.y, s1);
        s2 = fmaf(hs[k + 2], wv.z, s2);
        s3 = fmaf(hs[k + 3], wv.w, s3);
    }
    out[(size_t)b * OD + o] = (s0 + s1) + (s2 + s3) + bout[o];
}

// ---------------------------------------------------------------------------
extern "C" void kernel_launch(void* const* d_in, const int* in_sizes, int n_in,
                              void* d_out, int out_size)
{
    (void)in_sizes; (void)n_in; (void)out_size;
    const float* x    = (const float*)d_in[0];
    const float* Wih  = (const float*)d_in[1];
    const float* Whh  = (const float*)d_in[2];
    const float* bh   = (const float*)d_in[3];
    const float* Wout = (const float*)d_in[4];
    const float* bout = (const float*)d_in[5];
    float* out = (float*)d_out;

    cudaFuncSetAttribute(recur4_kernel,
                         cudaFuncAttributeMaxDynamicSharedMemorySize, R4_SMEM);
    cudaFuncSetAttribute(phase1_mma_kernel,
                         cudaFuncAttributeMaxDynamicSharedMemorySize, P1_SMEM_BYTES);

    init_kernel<<<256, 256>>>();
    split_w_kernel<<<256, 256>>>(Wih);
    split_x_kernel<<<2048, 256>>>(x);

    dim3 g1(8, 1024);                       // (HD/128, M/128) — n-block fastest
    phase1_mma_kernel<<<g1, 256, P1_SMEM_BYTES>>>(bh);

    recur4_kernel<<<128, 256, R4_SMEM>>>(Whh);

    out_kernel<<<dim3(BB, 4), 128>>>(Wout, bout, out);
}